// round 5
// baseline (speedup 1.0000x reference)
#include <cuda_runtime.h>
#include <cuda_bf16.h>
#include <cstdint>
#include <cstddef>
#include <cstring>

#define B_    256
#define D_    512
#define K_    128000
#define N_    100000
#define TOPK_  5
#define TOPKP_ 10
#define CAND_  32
#define FLTMAX 3.402823466e+38f

// GEMM tiling
#define BM 256
#define BN 128
#define BK 32
#define SA 40                     // padded smem row stride (bf16 units), 80 bytes
#define ABYTES (BM * SA * 2)      // 20480
#define BBYTES (BN * SA * 2)      // 10240
#define STAGE  (ABYTES + BBYTES)  // 30720
#define DSMEM  (2 * STAGE)        // 61440

// ---------------- device scratch ----------------
__device__ __align__(16) float g_St [32768000];
__device__ __align__(16) float g_Stp[32768000];
__device__ __align__(16) float g_tnorm[B_ * D_];
__device__ __align__(16) float g_qnorm[B_ * D_];
__device__ __align__(16) float g_ct   [B_ * D_];
__device__ __align__(16) __nv_bfloat16 g_tb[B_ * D_];
__device__ __align__(16) __nv_bfloat16 g_cb[B_ * D_];
__device__ int   g_eq[N_];
__device__ int   g_cand1[B_ * CAND_], g_cand2[B_ * CAND_];
__device__ int   g_unidx[B_ * TOPK_], g_idxp[B_ * TOPKP_];
__device__ float g_pb_un[B_], g_pb_con[B_], g_pb_pur[B_];

// ---------------- MMA helpers (sm_80+ features only) ----------------
__device__ __forceinline__ void ldsm4(uint32_t* r, uint32_t addr) {
    asm volatile("ldmatrix.sync.aligned.m8n8.x4.shared.b16 {%0,%1,%2,%3}, [%4];"
        : "=r"(r[0]), "=r"(r[1]), "=r"(r[2]), "=r"(r[3]) : "r"(addr));
}
__device__ __forceinline__ void mma16816(float* c,
        uint32_t a0, uint32_t a1, uint32_t a2, uint32_t a3,
        uint32_t b0, uint32_t b1) {
    asm volatile(
        "mma.sync.aligned.m16n8k16.row.col.f32.bf16.bf16.f32 "
        "{%0,%1,%2,%3}, {%4,%5,%6,%7}, {%8,%9}, {%0,%1,%2,%3};"
        : "+f"(c[0]), "+f"(c[1]), "+f"(c[2]), "+f"(c[3])
        : "r"(a0), "r"(a1), "r"(a2), "r"(a3), "r"(b0), "r"(b1));
}
#define CP_ASYNC16(dst_u32, src_ptr) \
    asm volatile("cp.async.cg.shared.global [%0], [%1], 16;" \
        :: "r"(dst_u32), "l"(src_ptr))
#define CP_COMMIT() asm volatile("cp.async.commit_group;" ::: "memory")
#define CP_WAIT0()  asm volatile("cp.async.wait_group 0;" ::: "memory")

// ---------------- prep kernels ----------------
__global__ void k_eq_copy(const int* __restrict__ pq) {
    int i = blockIdx.x * blockDim.x + threadIdx.x;
    if (i < N_) g_eq[i] = pq[i];
}
__global__ void k_eq_set(const int* __restrict__ indices, const int* __restrict__ pq) {
    int n = indices[threadIdx.x];
    g_eq[n] = 1 - pq[n];
}
__global__ void k_norm(const float* __restrict__ query, const float* __restrict__ ctgt) {
    int b = blockIdx.x, t = threadIdx.x;
    __shared__ float red[256];
    float x0 = query[b * D_ + t], x1 = query[b * D_ + t + 256];
    red[t] = x0 * x0 + x1 * x1;
    __syncthreads();
    for (int s = 128; s > 0; s >>= 1) { if (t < s) red[t] += red[t + s]; __syncthreads(); }
    float nq = sqrtf(red[0]);
    __syncthreads();
    g_qnorm[b * D_ + t] = x0 / nq;
    g_qnorm[b * D_ + t + 256] = x1 / nq;
    float y0 = ctgt[b * D_ + t], y1 = ctgt[b * D_ + t + 256];
    red[t] = y0 * y0 + y1 * y1;
    __syncthreads();
    for (int s = 128; s > 0; s >>= 1) { if (t < s) red[t] += red[t + s]; __syncthreads(); }
    float nt = sqrtf(red[0]);
    __syncthreads();
    float t0 = y0 / nt, t1 = y1 / nt;
    g_tnorm[b * D_ + t] = t0;
    g_tnorm[b * D_ + t + 256] = t1;
    g_tb[b * D_ + t] = __float2bfloat16(t0);
    g_tb[b * D_ + t + 256] = __float2bfloat16(t1);
}
__global__ void k_gather_ct(const float* __restrict__ pool, const int* __restrict__ indices) {
    int b = blockIdx.x, t = threadIdx.x;  // 128 threads
    int n = indices[b];
    const float4* src = (const float4*)(pool + ((size_t)g_eq[n] * N_ + (size_t)n) * D_);
    float4 v = src[t];
    ((float4*)(g_ct + b * D_))[t] = v;
    __nv_bfloat162 p0 = __floats2bfloat162_rn(v.x, v.y);
    __nv_bfloat162 p1 = __floats2bfloat162_rn(v.z, v.w);
    uint2 u; u.x = *(uint32_t*)&p0; u.y = *(uint32_t*)&p1;
    ((uint2*)(g_cb + b * D_))[t] = u;
}

// ---------------- bf16 mma.sync score GEMM ----------------
// Scores (approx): out[row][k] = 2 - 2 * <A_row, B_k>, A/B in bf16, fp32 accum.
// MODE 0: A = g_tb, Brow(k) = k<256 ? tnorm[k] : queue[k]     -> g_St
// MODE 1: A = g_cb, Brow(k) = pool[eq[ik], ik]                 -> g_Stp
template <int MODE>
__global__ __launch_bounds__(256, 1)
void k_gemm_mma(const float* __restrict__ queue, const float* __restrict__ pool,
                const int* __restrict__ indices, const int* __restrict__ index_queue,
                float* __restrict__ out) {
    extern __shared__ __align__(16) char smem[];
    __shared__ const float* rowp[BN];

    const int tid  = threadIdx.x;
    const int lane = tid & 31, wid = tid >> 5;
    const int wm = wid >> 1, wn = wid & 1;          // 4 x 2 warp grid
    const int bn = blockIdx.x * BN;
    const uint32_t smem_u = (uint32_t)__cvta_generic_to_shared(smem);

    if (tid < BN) {
        int kg = bn + tid;
        const float* p;
        if (MODE == 0) {
            p = (kg < B_) ? (g_tnorm + kg * D_) : (queue + (size_t)kg * D_);
        } else {
            int ik = (kg < B_) ? indices[kg] : index_queue[kg];
            p = pool + ((size_t)g_eq[ik] * N_ + (size_t)ik) * D_;
        }
        rowp[tid] = p;
    }
    __syncthreads();

    const __nv_bfloat16* Ab = (MODE == 0) ? g_tb : g_cb;
    const int br = tid >> 3, bc = tid & 7;          // B tile: rows br+32i, 16B chunk bc

    float acc[4][8][4];
#pragma unroll
    for (int a = 0; a < 4; a++)
#pragma unroll
        for (int b = 0; b < 8; b++)
#pragma unroll
            for (int c = 0; c < 4; c++) acc[a][b][c] = 0.f;

    float4 fb[4];

    // ---- prologue: stage 0 ----
#pragma unroll
    for (int i = 0; i < 4; i++)
        fb[i] = *(const float4*)(rowp[br + 32 * i] + bc * 4);
#pragma unroll
    for (int i = 0; i < 4; i++) {
        int q = i * 256 + tid, row = q >> 2, ch = q & 3;
        CP_ASYNC16(smem_u + row * 80 + ch * 16, Ab + (size_t)row * D_ + ch * 8);
    }
    CP_COMMIT();
#pragma unroll
    for (int i = 0; i < 4; i++) {
        __nv_bfloat162 h0 = __floats2bfloat162_rn(fb[i].x, fb[i].y);
        __nv_bfloat162 h1 = __floats2bfloat162_rn(fb[i].z, fb[i].w);
        uint2 u; u.x = *(uint32_t*)&h0; u.y = *(uint32_t*)&h1;
        *(uint2*)(smem + ABYTES + (br + 32 * i) * 80 + bc * 8) = u;
    }
    CP_WAIT0();
    __syncthreads();

    // ---- main loop: 16 K-chunks of 32 ----
    for (int it = 0; it < 16; ++it) {
        const int s = it & 1;
        if (it < 15) {
            const int kk = (it + 1) * BK;
#pragma unroll
            for (int i = 0; i < 4; i++)
                fb[i] = *(const float4*)(rowp[br + 32 * i] + kk + bc * 4);
        }
        // compute on buffer s
        {
            const uint32_t As_u = smem_u + s * STAGE;
            const uint32_t Bs_u = As_u + ABYTES;
            const int lrow = lane & 15, lhi = lane >> 4;
#pragma unroll
            for (int ks = 0; ks < 2; ks++) {
                uint32_t af[4][4], bf[4][4];
#pragma unroll
                for (int mt = 0; mt < 4; mt++)
                    ldsm4(af[mt], As_u + (wm * 64 + mt * 16 + lrow) * 80 + ks * 32 + lhi * 16);
#pragma unroll
                for (int np = 0; np < 4; np++)
                    ldsm4(bf[np], Bs_u + (wn * 64 + np * 16 + lrow) * 80 + ks * 32 + lhi * 16);
#pragma unroll
                for (int mt = 0; mt < 4; mt++)
#pragma unroll
                    for (int np = 0; np < 4; np++) {
                        mma16816(acc[mt][2 * np],
                                 af[mt][0], af[mt][1], af[mt][2], af[mt][3],
                                 bf[np][0], bf[np][2]);
                        mma16816(acc[mt][2 * np + 1],
                                 af[mt][0], af[mt][1], af[mt][2], af[mt][3],
                                 bf[np][1], bf[np][3]);
                    }
            }
        }
        __syncthreads();
        if (it < 15) {
            const int s2 = s ^ 1;
            const int kk = (it + 1) * BK;
#pragma unroll
            for (int i = 0; i < 4; i++) {
                int q = i * 256 + tid, row = q >> 2, ch = q & 3;
                CP_ASYNC16(smem_u + s2 * STAGE + row * 80 + ch * 16,
                           Ab + (size_t)row * D_ + kk + ch * 8);
            }
            CP_COMMIT();
#pragma unroll
            for (int i = 0; i < 4; i++) {
                __nv_bfloat162 h0 = __floats2bfloat162_rn(fb[i].x, fb[i].y);
                __nv_bfloat162 h1 = __floats2bfloat162_rn(fb[i].z, fb[i].w);
                uint2 u; u.x = *(uint32_t*)&h0; u.y = *(uint32_t*)&h1;
                *(uint2*)(smem + s2 * STAGE + ABYTES + (br + 32 * i) * 80 + bc * 8) = u;
            }
            CP_WAIT0();
            __syncthreads();
        }
    }

    // ---- epilogue: dist = 2 - 2*ip ----
#pragma unroll
    for (int mt = 0; mt < 4; mt++) {
        int r0 = wm * 64 + mt * 16 + (lane >> 2);
#pragma unroll
        for (int nt = 0; nt < 8; nt++) {
            int c = bn + wn * 64 + nt * 8 + (lane & 3) * 2;
            float2 v0, v1;
            v0.x = 2.f - 2.f * acc[mt][nt][0];
            v0.y = 2.f - 2.f * acc[mt][nt][1];
            v1.x = 2.f - 2.f * acc[mt][nt][2];
            v1.y = 2.f - 2.f * acc[mt][nt][3];
            *(float2*)(out + (size_t)r0 * K_ + c)       = v0;
            *(float2*)(out + (size_t)(r0 + 8) * K_ + c) = v1;
        }
    }
}

// ---------------- approx top-CAND (smallest value, ties -> smaller index) ----------------
template <int T>
__global__ void k_topk(const float* __restrict__ S, int* __restrict__ outIdx) {
    int b = blockIdx.x;
    const float4* row = (const float4*)(S + (size_t)b * K_);
    float v[T]; int id[T];
#pragma unroll
    for (int i = 0; i < T; i++) { v[i] = FLTMAX; id[i] = 0x7fffffff; }
    float thr = FLTMAX;
    for (int k4 = threadIdx.x; k4 < K_ / 4; k4 += 256) {
        float4 x = row[k4];
        float xs[4] = {x.x, x.y, x.z, x.w};
#pragma unroll
        for (int j = 0; j < 4; j++) {
            float xv = xs[j];
            if (xv < thr) {   // per-thread k increasing -> strict < keeps earliest
                int k = k4 * 4 + j;
                int pos = T - 1;
                while (pos > 0 && xv < v[pos - 1]) {
                    v[pos] = v[pos - 1]; id[pos] = id[pos - 1]; pos--;
                }
                v[pos] = xv; id[pos] = k;
                thr = v[T - 1];
            }
        }
    }
    __shared__ float swv[8]; __shared__ int swi[8];
    __shared__ int bwi_s;
    int hp = 0;
    for (int r = 0; r < T; r++) {
        float mv = (hp < T) ? v[hp] : FLTMAX;
        int   mi = (hp < T) ? id[hp] : 0x7fffffff;
        for (int o = 16; o > 0; o >>= 1) {
            float ov = __shfl_down_sync(0xffffffffu, mv, o);
            int   oi = __shfl_down_sync(0xffffffffu, mi, o);
            if (ov < mv || (ov == mv && oi < mi)) { mv = ov; mi = oi; }
        }
        if ((threadIdx.x & 31) == 0) { swv[threadIdx.x >> 5] = mv; swi[threadIdx.x >> 5] = mi; }
        __syncthreads();
        if (threadIdx.x == 0) {
            float bv = swv[0]; int bi = swi[0];
            for (int w = 1; w < 8; w++)
                if (swv[w] < bv || (swv[w] == bv && swi[w] < bi)) { bv = swv[w]; bi = swi[w]; }
            bwi_s = bi;
            outIdx[b * T + r] = bi;
        }
        __syncthreads();
        if (hp < T && id[hp] == bwi_s) hp++;
        __syncthreads();
    }
}

// ---------------- exact refine: rank CAND_ candidates by exact fp32 dist ----------------
template <int MODE, int T>
__global__ void k_refine(const float* __restrict__ queue, const float* __restrict__ pool,
                         const int* __restrict__ indices, const int* __restrict__ index_queue,
                         const int* __restrict__ cand, int* __restrict__ outIdx) {
    int b = blockIdx.x, t = threadIdx.x;
    __shared__ float sv[CAND_];
    __shared__ float red[256];
    const float* ar = (MODE == 0) ? (g_tnorm + b * D_) : (g_ct + b * D_);
    for (int j = 0; j < CAND_; j++) {
        int k = cand[b * CAND_ + j];
        const float* rk;
        if (MODE == 0) rk = (k < B_) ? (g_tnorm + k * D_) : (queue + (size_t)k * D_);
        else {
            int ik = (k < B_) ? indices[k] : index_queue[k];
            rk = pool + ((size_t)g_eq[ik] * N_ + (size_t)ik) * D_;
        }
        red[t] = ar[t] * rk[t] + ar[t + 256] * rk[t + 256];
        __syncthreads();
        for (int s = 128; s > 0; s >>= 1) { if (t < s) red[t] += red[t + s]; __syncthreads(); }
        if (t == 0) sv[j] = 2.f - 2.f * red[0];
        __syncthreads();
    }
    if (t == 0) {
        float vl[CAND_]; int il[CAND_];
        for (int j = 0; j < CAND_; j++) { vl[j] = sv[j]; il[j] = cand[b * CAND_ + j]; }
        for (int r = 0; r < T; r++) {
            int best = r;
            for (int j = r + 1; j < CAND_; j++)
                if (vl[j] < vl[best] || (vl[j] == vl[best] && il[j] < il[best])) best = j;
            float tv = vl[r]; vl[r] = vl[best]; vl[best] = tv;
            int ti = il[r]; il[r] = il[best]; il[best] = ti;
            outIdx[b * T + r] = il[r];
        }
    }
}

// ---------------- final: exact con-select + loss dots + purity ----------------
__global__ void k_final(const float* __restrict__ queue,
                        const int* __restrict__ labels_bank,
                        const int* __restrict__ labels) {
    int b = blockIdx.x, t = threadIdx.x;
    __shared__ float red[256];
    __shared__ float pv[TOPKP_];
    __shared__ int conIdx[TOPK_];
    const float* qr = g_qnorm + b * D_;
    const float* tr = g_tnorm + b * D_;
    for (int j = 0; j < TOPKP_; j++) {
        int k = g_idxp[b * TOPKP_ + j];
        const float* rk = (k < B_) ? (g_tnorm + k * D_) : (queue + (size_t)k * D_);
        red[t] = tr[t] * rk[t] + tr[t + 256] * rk[t + 256];
        __syncthreads();
        for (int s = 128; s > 0; s >>= 1) { if (t < s) red[t] += red[t + s]; __syncthreads(); }
        if (t == 0) pv[j] = 2.f - 2.f * red[0];
        __syncthreads();
    }
    if (t == 0) {
        float vl[TOPKP_]; int il[TOPKP_];
        for (int j = 0; j < TOPKP_; j++) { vl[j] = pv[j]; il[j] = g_idxp[b * TOPKP_ + j]; }
        for (int r = 0; r < TOPK_; r++) {
            int best = r;
            for (int j = r + 1; j < TOPKP_; j++)
                if (vl[j] < vl[best] || (vl[j] == vl[best] && il[j] < il[best])) best = j;
            float tv = vl[r]; vl[r] = vl[best]; vl[best] = tv;
            int ti = il[r]; il[r] = il[best]; il[best] = ti;
            conIdx[r] = il[r];
        }
    }
    __syncthreads();
    __shared__ float s_un, s_con;
    __shared__ int s_match;
    if (t == 0) { s_un = 0.f; s_con = 0.f; s_match = 0; }
    __syncthreads();
    for (int j = 0; j < 2 * TOPK_; j++) {
        int k = (j < TOPK_) ? g_unidx[b * TOPK_ + j] : conIdx[j - TOPK_];
        const float* rk = (k < B_) ? (g_tnorm + k * D_) : (queue + (size_t)k * D_);
        red[t] = qr[t] * rk[t] + qr[t + 256] * rk[t + 256];
        __syncthreads();
        for (int s = 128; s > 0; s >>= 1) { if (t < s) red[t] += red[t + s]; __syncthreads(); }
        if (t == 0) {
            float d = 2.f - 2.f * red[0];
            if (j < TOPK_) {
                s_un += d;
                int lab = (k < B_) ? labels[k] : labels_bank[k];
                if (lab == labels[b]) s_match++;
            } else {
                s_con += d;
            }
        }
        __syncthreads();
    }
    if (t == 0) {
        g_pb_un[b]  = s_un / (float)TOPK_;
        g_pb_con[b] = s_con / (float)TOPK_;
        g_pb_pur[b] = (float)s_match / (float)TOPK_;
    }
}

__global__ void k_finalize(float* __restrict__ out, int out_size) {
    float su = 0.f, sc = 0.f, sp = 0.f;
    for (int b = 0; b < B_; b++) { su += g_pb_un[b]; sc += g_pb_con[b]; sp += g_pb_pur[b]; }
    float loss = (sc / (float)B_ + su / (float)B_) * 0.5f;
    out[0] = loss;
    if (out_size > 1) out[1] = sp / (float)B_;
}

// ---------------- launch ----------------
extern "C" void kernel_launch(void* const* d_in, const int* in_sizes, int n_in,
                              void* d_out, int out_size) {
    const float* query       = (const float*)d_in[0];
    const float* ctgt        = (const float*)d_in[1];
    const float* queue       = (const float*)d_in[2];
    const float* pool        = (const float*)d_in[3];
    const int*   labels_bank = (const int*)d_in[4];
    const int*   index_queue = (const int*)d_in[5];
    const int*   pool_qindex = (const int*)d_in[6];
    const int*   labels      = (const int*)d_in[7];
    const int*   indices     = (const int*)d_in[8];

    float* St_ptr;  cudaGetSymbolAddress((void**)&St_ptr,  g_St);
    float* Stp_ptr; cudaGetSymbolAddress((void**)&Stp_ptr, g_Stp);
    int* c1_ptr;    cudaGetSymbolAddress((void**)&c1_ptr,  g_cand1);
    int* c2_ptr;    cudaGetSymbolAddress((void**)&c2_ptr,  g_cand2);
    int* un_ptr;    cudaGetSymbolAddress((void**)&un_ptr,  g_unidx);
    int* ip_ptr;    cudaGetSymbolAddress((void**)&ip_ptr,  g_idxp);

    cudaFuncSetAttribute(k_gemm_mma<0>, cudaFuncAttributeMaxDynamicSharedMemorySize, DSMEM);
    cudaFuncSetAttribute(k_gemm_mma<1>, cudaFuncAttributeMaxDynamicSharedMemorySize, DSMEM);

    k_eq_copy<<<(N_ + 255) / 256, 256>>>(pool_qindex);
    k_eq_set<<<1, 256>>>(indices, pool_qindex);
    k_norm<<<B_, 256>>>(query, ctgt);
    k_gather_ct<<<B_, 128>>>(pool, indices);

    k_gemm_mma<0><<<K_ / BN, 256, DSMEM>>>(queue, pool, indices, index_queue, St_ptr);
    k_gemm_mma<1><<<K_ / BN, 256, DSMEM>>>(queue, pool, indices, index_queue, Stp_ptr);

    k_topk<CAND_><<<B_, 256>>>(St_ptr,  c1_ptr);
    k_topk<CAND_><<<B_, 256>>>(Stp_ptr, c2_ptr);

    k_refine<0, TOPK_ ><<<B_, 256>>>(queue, pool, indices, index_queue, c1_ptr, un_ptr);
    k_refine<1, TOPKP_><<<B_, 256>>>(queue, pool, indices, index_queue, c2_ptr, ip_ptr);

    k_final<<<B_, 256>>>(queue, labels_bank, labels);
    k_finalize<<<1, 1>>>((float*)d_out, out_size);
}

// round 6
// speedup vs baseline: 10.8773x; 10.8773x over previous
#include <cuda_runtime.h>
#include <cuda_bf16.h>
#include <cstdint>
#include <cstddef>

#define B_    256
#define D_    512
#define K_    128000
#define N_    100000
#define TOPK_  5
#define TOPKP_ 10
#define CAND_  32
#define TH_    8
#define FLTMAX 3.402823466e+38f

// GEMM tiling: BM=256, BN=128, BK=32, 8 warps (4M x 2N), warp tile 64x64
#define BN 128
#define AB_   20480                 // A stage bytes: 256 rows * 80
#define BB_   10240                 // B stage bytes: 128 rows * 80
#define STG   (AB_ + BB_)           // 30720
#define GSMEM (4 * STG)             // 122880 (4 stages)

// ---------------- device scratch ----------------
__device__ __align__(16) float g_St [32768000];
__device__ __align__(16) float g_Stp[32768000];
__device__ __align__(16) __nv_bfloat16 g_Bq[65536000];   // bf16 B for mode 0
__device__ __align__(16) __nv_bfloat16 g_Bp[65536000];   // bf16 B for mode 1
__device__ __align__(16) float g_tnorm[B_ * D_];
__device__ __align__(16) float g_qnorm[B_ * D_];
__device__ __align__(16) float g_ct   [B_ * D_];
__device__ __align__(16) __nv_bfloat16 g_tb[B_ * D_];
__device__ __align__(16) __nv_bfloat16 g_cb[B_ * D_];
__device__ int   g_eq[N_];
__device__ int   g_cand1[B_ * CAND_], g_cand2[B_ * CAND_];
__device__ int   g_unidx[B_ * TOPK_], g_idxp[B_ * TOPKP_];
__device__ float g_pb_un[B_], g_pb_con[B_], g_pb_pur[B_];

// ---------------- MMA / cp.async helpers (sm_80+ features only) ----------------
__device__ __forceinline__ void ldsm4(uint32_t* r, uint32_t addr) {
    asm volatile("ldmatrix.sync.aligned.m8n8.x4.shared.b16 {%0,%1,%2,%3}, [%4];"
        : "=r"(r[0]), "=r"(r[1]), "=r"(r[2]), "=r"(r[3]) : "r"(addr));
}
__device__ __forceinline__ void mma16816(float* c,
        uint32_t a0, uint32_t a1, uint32_t a2, uint32_t a3,
        uint32_t b0, uint32_t b1) {
    asm volatile(
        "mma.sync.aligned.m16n8k16.row.col.f32.bf16.bf16.f32 "
        "{%0,%1,%2,%3}, {%4,%5,%6,%7}, {%8,%9}, {%0,%1,%2,%3};"
        : "+f"(c[0]), "+f"(c[1]), "+f"(c[2]), "+f"(c[3])
        : "r"(a0), "r"(a1), "r"(a2), "r"(a3), "r"(b0), "r"(b1));
}
#define CP_ASYNC16(dst_u32, src_ptr) \
    asm volatile("cp.async.cg.shared.global [%0], [%1], 16;" \
        :: "r"(dst_u32), "l"(src_ptr))
#define CP_COMMIT() asm volatile("cp.async.commit_group;" ::: "memory")
#define CP_WAIT0()  asm volatile("cp.async.wait_group 0;" ::: "memory")
#define CP_WAIT1()  asm volatile("cp.async.wait_group 1;" ::: "memory")
#define CP_WAIT2()  asm volatile("cp.async.wait_group 2;" ::: "memory")

// ---------------- prep kernels ----------------
__global__ void k_eq_copy(const int* __restrict__ pq) {
    int i = blockIdx.x * blockDim.x + threadIdx.x;
    if (i < N_) g_eq[i] = pq[i];
}
__global__ void k_eq_set(const int* __restrict__ indices, const int* __restrict__ pq) {
    int n = indices[threadIdx.x];
    g_eq[n] = 1 - pq[n];
}
__global__ void k_norm(const float* __restrict__ query, const float* __restrict__ ctgt) {
    int b = blockIdx.x, t = threadIdx.x;
    __shared__ float red[256];
    float x0 = query[b * D_ + t], x1 = query[b * D_ + t + 256];
    red[t] = x0 * x0 + x1 * x1;
    __syncthreads();
    for (int s = 128; s > 0; s >>= 1) { if (t < s) red[t] += red[t + s]; __syncthreads(); }
    float nq = sqrtf(red[0]);
    __syncthreads();
    g_qnorm[b * D_ + t] = x0 / nq;
    g_qnorm[b * D_ + t + 256] = x1 / nq;
    float y0 = ctgt[b * D_ + t], y1 = ctgt[b * D_ + t + 256];
    red[t] = y0 * y0 + y1 * y1;
    __syncthreads();
    for (int s = 128; s > 0; s >>= 1) { if (t < s) red[t] += red[t + s]; __syncthreads(); }
    float nt = sqrtf(red[0]);
    __syncthreads();
    float t0 = y0 / nt, t1 = y1 / nt;
    g_tnorm[b * D_ + t] = t0;
    g_tnorm[b * D_ + t + 256] = t1;
    g_tb[b * D_ + t] = __float2bfloat16(t0);
    g_tb[b * D_ + t + 256] = __float2bfloat16(t1);
}
__global__ void k_gather_ct(const float* __restrict__ pool, const int* __restrict__ indices) {
    int b = blockIdx.x, t = threadIdx.x;  // 128 threads
    int n = indices[b];
    const float4* src = (const float4*)(pool + ((size_t)g_eq[n] * N_ + (size_t)n) * D_);
    float4 v = src[t];
    ((float4*)(g_ct + b * D_))[t] = v;
    __nv_bfloat162 p0 = __floats2bfloat162_rn(v.x, v.y);
    __nv_bfloat162 p1 = __floats2bfloat162_rn(v.z, v.w);
    uint2 u; u.x = *(uint32_t*)&p0; u.y = *(uint32_t*)&p1;
    ((uint2*)(g_cb + b * D_))[t] = u;
}

// ---------------- B conversion: fp32 rows (with gather/override) -> contiguous bf16 ----------------
// MODE 0: row k -> (k<256 ? tnorm[k] : queue[k])
// MODE 1: row k -> pool[eq[ik], ik],  ik = (k<256 ? indices[k] : index_queue[k])
template <int MODE>
__global__ __launch_bounds__(256)
void k_conv(const float* __restrict__ queue, const float* __restrict__ pool,
            const int* __restrict__ indices, const int* __restrict__ index_queue,
            __nv_bfloat16* __restrict__ out) {
    int gw = (blockIdx.x * blockDim.x + threadIdx.x) >> 5;   // global warp, 8000 total
    int lane = threadIdx.x & 31;
#pragma unroll 1
    for (int r = 0; r < 16; r++) {
        int k = gw * 16 + r;
        if (k >= K_) return;
        const float* src;
        if (MODE == 0) {
            src = (k < B_) ? (g_tnorm + k * D_) : (queue + (size_t)k * D_);
        } else {
            int ik = (k < B_) ? indices[k] : index_queue[k];
            src = pool + ((size_t)g_eq[ik] * N_ + (size_t)ik) * D_;
        }
        uint2* dst = (uint2*)(out + (size_t)k * D_);
#pragma unroll
        for (int it = 0; it < 4; it++) {
            float4 v = ((const float4*)src)[it * 32 + lane];
            __nv_bfloat162 p0 = __floats2bfloat162_rn(v.x, v.y);
            __nv_bfloat162 p1 = __floats2bfloat162_rn(v.z, v.w);
            uint2 u; u.x = *(uint32_t*)&p0; u.y = *(uint32_t*)&p1;
            dst[it * 32 + lane] = u;
        }
    }
}

// ---------------- pipelined bf16 mma.sync GEMM: out = 2 - 2 * A(256xD) * B^T ----------------
__global__ __launch_bounds__(256, 1)
void k_gemm2(const __nv_bfloat16* __restrict__ Ab, const __nv_bfloat16* __restrict__ Bb,
             float* __restrict__ out) {
    extern __shared__ __align__(16) char smem[];
    const int tid  = threadIdx.x;
    const int lane = tid & 31, wid = tid >> 5;
    const int wm = wid >> 1, wn = wid & 1;
    const int bn = blockIdx.x * BN;
    const uint32_t smem_u = (uint32_t)__cvta_generic_to_shared(smem);

    float acc[4][8][4];
#pragma unroll
    for (int a = 0; a < 4; a++)
#pragma unroll
        for (int b = 0; b < 8; b++)
#pragma unroll
            for (int c = 0; c < 4; c++) acc[a][b][c] = 0.f;

    const int qrow = tid >> 2, qc = tid & 3;   // loader: 4 chunks of 16B per row

    // stage issue: A 256 rows x 64B (4 chunks), B 128 rows x 64B
#define ISSUE(s, kk) do { \
        uint32_t base_ = smem_u + (s) * STG; \
        _Pragma("unroll") \
        for (int i_ = 0; i_ < 4; i_++) { \
            int row_ = qrow + i_ * 64; \
            CP_ASYNC16(base_ + row_ * 80 + qc * 16, Ab + (size_t)row_ * D_ + (kk) + qc * 8); \
        } \
        uint32_t bb_ = base_ + AB_; \
        _Pragma("unroll") \
        for (int i_ = 0; i_ < 2; i_++) { \
            int row_ = qrow + i_ * 64; \
            CP_ASYNC16(bb_ + row_ * 80 + qc * 16, Bb + (size_t)(bn + row_) * D_ + (kk) + qc * 8); \
        } \
        CP_COMMIT(); \
    } while (0)

    ISSUE(0, 0); ISSUE(1, 32); ISSUE(2, 64);

    const int lrow = lane & 15, lhi = lane >> 4;
#pragma unroll 1
    for (int it = 0; it < 16; ++it) {
        if (it < 14) CP_WAIT2(); else if (it == 14) CP_WAIT1(); else CP_WAIT0();
        __syncthreads();
        const int s = it & 3;
        const uint32_t As_u = smem_u + s * STG;
        const uint32_t Bs_u = As_u + AB_;
#pragma unroll
        for (int ks = 0; ks < 2; ks++) {
            uint32_t af[4][4], bf[4][4];
#pragma unroll
            for (int mt = 0; mt < 4; mt++)
                ldsm4(af[mt], As_u + (wm * 64 + mt * 16 + lrow) * 80 + ks * 32 + lhi * 16);
#pragma unroll
            for (int np = 0; np < 4; np++)
                ldsm4(bf[np], Bs_u + (wn * 64 + np * 16 + lrow) * 80 + ks * 32 + lhi * 16);
#pragma unroll
            for (int mt = 0; mt < 4; mt++)
#pragma unroll
                for (int np = 0; np < 4; np++) {
                    mma16816(acc[mt][2 * np],
                             af[mt][0], af[mt][1], af[mt][2], af[mt][3],
                             bf[np][0], bf[np][2]);
                    mma16816(acc[mt][2 * np + 1],
                             af[mt][0], af[mt][1], af[mt][2], af[mt][3],
                             bf[np][1], bf[np][3]);
                }
        }
        int nx = it + 3;
        if (nx < 16) ISSUE(nx & 3, nx * 32);
    }
#undef ISSUE

    // epilogue: dist = 2 - 2*ip
#pragma unroll
    for (int mt = 0; mt < 4; mt++) {
        int r0 = wm * 64 + mt * 16 + (lane >> 2);
#pragma unroll
        for (int nt = 0; nt < 8; nt++) {
            int c = bn + wn * 64 + nt * 8 + (lane & 3) * 2;
            float2 v0, v1;
            v0.x = 2.f - 2.f * acc[mt][nt][0];
            v0.y = 2.f - 2.f * acc[mt][nt][1];
            v1.x = 2.f - 2.f * acc[mt][nt][2];
            v1.y = 2.f - 2.f * acc[mt][nt][3];
            *(float2*)(out + (size_t)r0 * K_ + c)       = v0;
            *(float2*)(out + (size_t)(r0 + 8) * K_ + c) = v1;
        }
    }
}

// ---------------- approx top-CAND per row (512 threads, per-thread depth 8) ----------------
// smallest values; ties -> smaller index (within thread: first occurrence kept;
// across threads: explicit index tie-break)
__global__ __launch_bounds__(512)
void k_topk(const float* __restrict__ S, int* __restrict__ outIdx) {
    int b = blockIdx.x;
    const float4* row = (const float4*)(S + (size_t)b * K_);
    float v[TH_]; int id[TH_];
#pragma unroll
    for (int i = 0; i < TH_; i++) { v[i] = FLTMAX; id[i] = 0x7fffffff; }
    float thr = FLTMAX;
    for (int k4 = threadIdx.x; k4 < K_ / 4; k4 += 512) {
        float4 x = row[k4];
        float xs[4] = {x.x, x.y, x.z, x.w};
#pragma unroll
        for (int j = 0; j < 4; j++) {
            float xv = xs[j];
            if (xv < thr) {
                int k = k4 * 4 + j;
                int pos = TH_ - 1;
                while (pos > 0 && xv < v[pos - 1]) {
                    v[pos] = v[pos - 1]; id[pos] = id[pos - 1]; pos--;
                }
                v[pos] = xv; id[pos] = k;
                thr = v[TH_ - 1];
            }
        }
    }
    __shared__ float swv[16]; __shared__ int swi[16];
    __shared__ int bwi_s;
    int hp = 0;
    for (int r = 0; r < CAND_; r++) {
        float mv = (hp < TH_) ? v[hp] : FLTMAX;
        int   mi = (hp < TH_) ? id[hp] : 0x7fffffff;
        for (int o = 16; o > 0; o >>= 1) {
            float ov = __shfl_down_sync(0xffffffffu, mv, o);
            int   oi = __shfl_down_sync(0xffffffffu, mi, o);
            if (ov < mv || (ov == mv && oi < mi)) { mv = ov; mi = oi; }
        }
        if ((threadIdx.x & 31) == 0) { swv[threadIdx.x >> 5] = mv; swi[threadIdx.x >> 5] = mi; }
        __syncthreads();
        if (threadIdx.x == 0) {
            float bv = swv[0]; int bi = swi[0];
            for (int w = 1; w < 16; w++)
                if (swv[w] < bv || (swv[w] == bv && swi[w] < bi)) { bv = swv[w]; bi = swi[w]; }
            bwi_s = bi;
            outIdx[b * CAND_ + r] = bi;
        }
        __syncthreads();
        if (hp < TH_ && id[hp] == bwi_s) hp++;
        __syncthreads();
    }
}

// ---------------- exact refine: warp-per-candidate fp32 dots, then select T ----------------
template <int MODE, int T>
__global__ void k_refine(const float* __restrict__ queue, const float* __restrict__ pool,
                         const int* __restrict__ indices, const int* __restrict__ index_queue,
                         const int* __restrict__ cand, int* __restrict__ outIdx) {
    int b = blockIdx.x;
    int lane = threadIdx.x & 31, w = threadIdx.x >> 5;   // 8 warps
    __shared__ float sv[CAND_];
    const float* ar = (MODE == 0) ? (g_tnorm + b * D_) : (g_ct + b * D_);
    for (int j = w; j < CAND_; j += 8) {
        int k = cand[b * CAND_ + j];
        const float* rk;
        if (MODE == 0) rk = (k < B_) ? (g_tnorm + k * D_) : (queue + (size_t)k * D_);
        else {
            int ik = (k < B_) ? indices[k] : index_queue[k];
            rk = pool + ((size_t)g_eq[ik] * N_ + (size_t)ik) * D_;
        }
        float s = 0.f;
#pragma unroll
        for (int t = 0; t < 16; t++) { int i = t * 32 + lane; s += ar[i] * rk[i]; }
        for (int o = 16; o > 0; o >>= 1) s += __shfl_down_sync(0xffffffffu, s, o);
        if (lane == 0) sv[j] = 2.f - 2.f * s;
    }
    __syncthreads();
    if (threadIdx.x == 0) {
        float vl[CAND_]; int il[CAND_];
        for (int j = 0; j < CAND_; j++) { vl[j] = sv[j]; il[j] = cand[b * CAND_ + j]; }
        for (int r = 0; r < T; r++) {
            int best = r;
            for (int j = r + 1; j < CAND_; j++)
                if (vl[j] < vl[best] || (vl[j] == vl[best] && il[j] < il[best])) best = j;
            float tv = vl[r]; vl[r] = vl[best]; vl[best] = tv;
            int ti = il[r]; il[r] = il[best]; il[best] = ti;
            outIdx[b * T + r] = il[r];
        }
    }
}

// ---------------- final: exact con-select + loss dots + purity ----------------
__global__ void k_final(const float* __restrict__ queue,
                        const int* __restrict__ labels_bank,
                        const int* __restrict__ labels) {
    int b = blockIdx.x, t = threadIdx.x;
    __shared__ float red[256];
    __shared__ float pv[TOPKP_];
    __shared__ int conIdx[TOPK_];
    const float* qr = g_qnorm + b * D_;
    const float* tr = g_tnorm + b * D_;
    for (int j = 0; j < TOPKP_; j++) {
        int k = g_idxp[b * TOPKP_ + j];
        const float* rk = (k < B_) ? (g_tnorm + k * D_) : (queue + (size_t)k * D_);
        red[t] = tr[t] * rk[t] + tr[t + 256] * rk[t + 256];
        __syncthreads();
        for (int s = 128; s > 0; s >>= 1) { if (t < s) red[t] += red[t + s]; __syncthreads(); }
        if (t == 0) pv[j] = 2.f - 2.f * red[0];
        __syncthreads();
    }
    if (t == 0) {
        float vl[TOPKP_]; int il[TOPKP_];
        for (int j = 0; j < TOPKP_; j++) { vl[j] = pv[j]; il[j] = g_idxp[b * TOPKP_ + j]; }
        for (int r = 0; r < TOPK_; r++) {
            int best = r;
            for (int j = r + 1; j < TOPKP_; j++)
                if (vl[j] < vl[best] || (vl[j] == vl[best] && il[j] < il[best])) best = j;
            float tv = vl[r]; vl[r] = vl[best]; vl[best] = tv;
            int ti = il[r]; il[r] = il[best]; il[best] = ti;
            conIdx[r] = il[r];
        }
    }
    __syncthreads();
    __shared__ float s_un, s_con;
    __shared__ int s_match;
    if (t == 0) { s_un = 0.f; s_con = 0.f; s_match = 0; }
    __syncthreads();
    for (int j = 0; j < 2 * TOPK_; j++) {
        int k = (j < TOPK_) ? g_unidx[b * TOPK_ + j] : conIdx[j - TOPK_];
        const float* rk = (k < B_) ? (g_tnorm + k * D_) : (queue + (size_t)k * D_);
        red[t] = qr[t] * rk[t] + qr[t + 256] * rk[t + 256];
        __syncthreads();
        for (int s = 128; s > 0; s >>= 1) { if (t < s) red[t] += red[t + s]; __syncthreads(); }
        if (t == 0) {
            float d = 2.f - 2.f * red[0];
            if (j < TOPK_) {
                s_un += d;
                int lab = (k < B_) ? labels[k] : labels_bank[k];
                if (lab == labels[b]) s_match++;
            } else {
                s_con += d;
            }
        }
        __syncthreads();
    }
    if (t == 0) {
        g_pb_un[b]  = s_un / (float)TOPK_;
        g_pb_con[b] = s_con / (float)TOPK_;
        g_pb_pur[b] = (float)s_match / (float)TOPK_;
    }
}

__global__ void k_finalize(float* __restrict__ out, int out_size) {
    float su = 0.f, sc = 0.f, sp = 0.f;
    for (int b = 0; b < B_; b++) { su += g_pb_un[b]; sc += g_pb_con[b]; sp += g_pb_pur[b]; }
    float loss = (sc / (float)B_ + su / (float)B_) * 0.5f;
    out[0] = loss;
    if (out_size > 1) out[1] = sp / (float)B_;
}

// ---------------- launch ----------------
extern "C" void kernel_launch(void* const* d_in, const int* in_sizes, int n_in,
                              void* d_out, int out_size) {
    const float* query       = (const float*)d_in[0];
    const float* ctgt        = (const float*)d_in[1];
    const float* queue       = (const float*)d_in[2];
    const float* pool        = (const float*)d_in[3];
    const int*   labels_bank = (const int*)d_in[4];
    const int*   index_queue = (const int*)d_in[5];
    const int*   pool_qindex = (const int*)d_in[6];
    const int*   labels      = (const int*)d_in[7];
    const int*   indices     = (const int*)d_in[8];

    float* St_ptr;  cudaGetSymbolAddress((void**)&St_ptr,  g_St);
    float* Stp_ptr; cudaGetSymbolAddress((void**)&Stp_ptr, g_Stp);
    __nv_bfloat16* Bq_ptr; cudaGetSymbolAddress((void**)&Bq_ptr, g_Bq);
    __nv_bfloat16* Bp_ptr; cudaGetSymbolAddress((void**)&Bp_ptr, g_Bp);
    __nv_bfloat16* tb_ptr; cudaGetSymbolAddress((void**)&tb_ptr, g_tb);
    __nv_bfloat16* cb_ptr; cudaGetSymbolAddress((void**)&cb_ptr, g_cb);
    int* c1_ptr;    cudaGetSymbolAddress((void**)&c1_ptr,  g_cand1);
    int* c2_ptr;    cudaGetSymbolAddress((void**)&c2_ptr,  g_cand2);
    int* un_ptr;    cudaGetSymbolAddress((void**)&un_ptr,  g_unidx);
    int* ip_ptr;    cudaGetSymbolAddress((void**)&ip_ptr,  g_idxp);

    cudaFuncSetAttribute(k_gemm2, cudaFuncAttributeMaxDynamicSharedMemorySize, GSMEM);

    k_eq_copy<<<(N_ + 255) / 256, 256>>>(pool_qindex);
    k_eq_set<<<1, 256>>>(indices, pool_qindex);
    k_norm<<<B_, 256>>>(query, ctgt);
    k_gather_ct<<<B_, 128>>>(pool, indices);

    k_conv<0><<<1000, 256>>>(queue, pool, indices, index_queue, Bq_ptr);
    k_conv<1><<<1000, 256>>>(queue, pool, indices, index_queue, Bp_ptr);

    k_gemm2<<<K_ / BN, 256, GSMEM>>>(tb_ptr, Bq_ptr, St_ptr);
    k_gemm2<<<K_ / BN, 256, GSMEM>>>(cb_ptr, Bp_ptr, Stp_ptr);

    k_topk<<<B_, 512>>>(St_ptr,  c1_ptr);
    k_topk<<<B_, 512>>>(Stp_ptr, c2_ptr);

    k_refine<0, TOPK_ ><<<B_, 256>>>(queue, pool, indices, index_queue, c1_ptr, un_ptr);
    k_refine<1, TOPKP_><<<B_, 256>>>(queue, pool, indices, index_queue, c2_ptr, ip_ptr);

    k_final<<<B_, 256>>>(queue, labels_bank, labels);
    k_finalize<<<1, 1>>>((float*)d_out, out_size);
}

// round 7
// speedup vs baseline: 12.9445x; 1.1900x over previous
#include <cuda_runtime.h>
#include <cuda_bf16.h>
#include <cstdint>
#include <cstddef>

#define B_    256
#define D_    512
#define K_    128000
#define N_    100000
#define TOPK_  5
#define TOPKP_ 10
#define CAND_  32
#define TH_    8
#define FLTMAX 3.402823466e+38f

// GEMM tiling: BM=256, BN=128, BK=32, 8 warps (4M x 2N), warp tile 64x64
#define BN 128
#define ASTG  20480                 // A stage bytes: 256 rows * 80
#define BSTG  10240                 // B (bf16) stage bytes: 128 rows * 80
#define AOFF  0
#define BOFF  (4 * ASTG)            // 81920
#define GSMEM (4 * ASTG + 2 * BSTG) // 102400

// ---------------- device scratch ----------------
__device__ __align__(16) float g_St [32768000];
__device__ __align__(16) float g_Stp[32768000];
__device__ __align__(16) float g_tnorm[B_ * D_];
__device__ __align__(16) float g_qnorm[B_ * D_];
__device__ __align__(16) float g_ct   [B_ * D_];
__device__ __align__(16) __nv_bfloat16 g_tb[B_ * D_];
__device__ __align__(16) __nv_bfloat16 g_cb[B_ * D_];
__device__ int   g_eq[N_];
__device__ int   g_cand1[B_ * CAND_], g_cand2[B_ * CAND_];
__device__ int   g_unidx[B_ * TOPK_], g_idxp[B_ * TOPKP_];
__device__ float g_pb_un[B_], g_pb_con[B_], g_pb_pur[B_];

// ---------------- MMA / cp.async helpers ----------------
__device__ __forceinline__ void ldsm4(uint32_t* r, uint32_t addr) {
    asm volatile("ldmatrix.sync.aligned.m8n8.x4.shared.b16 {%0,%1,%2,%3}, [%4];"
        : "=r"(r[0]), "=r"(r[1]), "=r"(r[2]), "=r"(r[3]) : "r"(addr));
}
__device__ __forceinline__ void mma16816(float* c,
        uint32_t a0, uint32_t a1, uint32_t a2, uint32_t a3,
        uint32_t b0, uint32_t b1) {
    asm volatile(
        "mma.sync.aligned.m16n8k16.row.col.f32.bf16.bf16.f32 "
        "{%0,%1,%2,%3}, {%4,%5,%6,%7}, {%8,%9}, {%0,%1,%2,%3};"
        : "+f"(c[0]), "+f"(c[1]), "+f"(c[2]), "+f"(c[3])
        : "r"(a0), "r"(a1), "r"(a2), "r"(a3), "r"(b0), "r"(b1));
}
#define CP_ASYNC16(dst_u32, src_ptr) \
    asm volatile("cp.async.cg.shared.global [%0], [%1], 16;" \
        :: "r"(dst_u32), "l"(src_ptr))
#define CP_COMMIT() asm volatile("cp.async.commit_group;" ::: "memory")
#define CP_WAIT0()  asm volatile("cp.async.wait_group 0;" ::: "memory")
#define CP_WAIT1()  asm volatile("cp.async.wait_group 1;" ::: "memory")
#define CP_WAIT2()  asm volatile("cp.async.wait_group 2;" ::: "memory")

// ---------------- prep kernels ----------------
__global__ void k_eq_copy(const int* __restrict__ pq) {
    int i = blockIdx.x * blockDim.x + threadIdx.x;
    if (i < N_) g_eq[i] = pq[i];
}
__global__ void k_eq_set(const int* __restrict__ indices, const int* __restrict__ pq) {
    int n = indices[threadIdx.x];
    g_eq[n] = 1 - pq[n];
}
__global__ void k_norm(const float* __restrict__ query, const float* __restrict__ ctgt) {
    int b = blockIdx.x, t = threadIdx.x;
    __shared__ float red[256];
    float x0 = query[b * D_ + t], x1 = query[b * D_ + t + 256];
    red[t] = x0 * x0 + x1 * x1;
    __syncthreads();
    for (int s = 128; s > 0; s >>= 1) { if (t < s) red[t] += red[t + s]; __syncthreads(); }
    float nq = sqrtf(red[0]);
    __syncthreads();
    g_qnorm[b * D_ + t] = x0 / nq;
    g_qnorm[b * D_ + t + 256] = x1 / nq;
    float y0 = ctgt[b * D_ + t], y1 = ctgt[b * D_ + t + 256];
    red[t] = y0 * y0 + y1 * y1;
    __syncthreads();
    for (int s = 128; s > 0; s >>= 1) { if (t < s) red[t] += red[t + s]; __syncthreads(); }
    float nt = sqrtf(red[0]);
    __syncthreads();
    float t0 = y0 / nt, t1 = y1 / nt;
    g_tnorm[b * D_ + t] = t0;
    g_tnorm[b * D_ + t + 256] = t1;
    g_tb[b * D_ + t] = __float2bfloat16(t0);
    g_tb[b * D_ + t + 256] = __float2bfloat16(t1);
}
__global__ void k_gather_ct(const float* __restrict__ pool, const int* __restrict__ indices) {
    int b = blockIdx.x, t = threadIdx.x;  // 128 threads
    int n = indices[b];
    const float4* src = (const float4*)(pool + ((size_t)g_eq[n] * N_ + (size_t)n) * D_);
    float4 v = src[t];
    ((float4*)(g_ct + b * D_))[t] = v;
    __nv_bfloat162 p0 = __floats2bfloat162_rn(v.x, v.y);
    __nv_bfloat162 p1 = __floats2bfloat162_rn(v.z, v.w);
    uint2 u; u.x = *(uint32_t*)&p0; u.y = *(uint32_t*)&p1;
    ((uint2*)(g_cb + b * D_))[t] = u;
}

// ---------------- fused GEMM: B gathered fp32 -> bf16 in-kernel ----------------
// blockIdx.y = 0: A=g_tb, Brow(k)= k<256 ? tnorm[k] : queue[k],           out=g_St
// blockIdx.y = 1: A=g_cb, Brow(k)= pool[eq[ik],ik], ik per updated iq,    out=g_Stp
__global__ __launch_bounds__(256, 1)
void k_gemm3(const float* __restrict__ queue, const float* __restrict__ pool,
             const int* __restrict__ indices, const int* __restrict__ index_queue,
             float* __restrict__ outA, float* __restrict__ outB) {
    extern __shared__ __align__(16) char smem[];
    __shared__ const float* rowp[BN];

    const int my   = blockIdx.y;
    const int tid  = threadIdx.x;
    const int lane = tid & 31, wid = tid >> 5;
    const int wm = wid >> 1, wn = wid & 1;
    const int bn = blockIdx.x * BN;
    const uint32_t smem_u = (uint32_t)__cvta_generic_to_shared(smem);

    const __nv_bfloat16* Ab = (my == 0) ? g_tb : g_cb;
    float* out = (my == 0) ? outA : outB;

    if (tid < BN) {
        int kg = bn + tid;
        const float* p;
        if (my == 0) {
            p = (kg < B_) ? (g_tnorm + kg * D_) : (queue + (size_t)kg * D_);
        } else {
            int ik = (kg < B_) ? indices[kg] : index_queue[kg];
            p = pool + ((size_t)g_eq[ik] * N_ + (size_t)ik) * D_;
        }
        rowp[tid] = p;
    }
    __syncthreads();

    float acc[4][8][4];
#pragma unroll
    for (int a = 0; a < 4; a++)
#pragma unroll
        for (int b = 0; b < 8; b++)
#pragma unroll
            for (int c = 0; c < 4; c++) acc[a][b][c] = 0.f;

    const int qrow = tid >> 2, qc = tid & 3;     // A loader
    const int brow = tid >> 1, bhalf = tid & 1;  // B loader: 64B fp32 per thread
    const float* bptr = rowp[brow] + bhalf * 16;

#define ISSUE_A(s, kk) do { \
        uint32_t base_ = smem_u + (s) * ASTG; \
        _Pragma("unroll") \
        for (int i_ = 0; i_ < 4; i_++) { \
            int row_ = qrow + i_ * 64; \
            CP_ASYNC16(base_ + row_ * 80 + qc * 16, Ab + (size_t)row_ * D_ + (kk) + qc * 8); \
        } \
        CP_COMMIT(); \
    } while (0)

#define LOAD_B(kk) do { \
        _Pragma("unroll") \
        for (int j_ = 0; j_ < 4; j_++) fb[j_] = *(const float4*)(bptr + (kk) + j_ * 4); \
    } while (0)

#define STS_B(s) do { \
        char* dst_ = smem + BOFF + (s) * BSTG + brow * 80 + bhalf * 32; \
        _Pragma("unroll") \
        for (int j_ = 0; j_ < 4; j_++) { \
            __nv_bfloat162 h0_ = __floats2bfloat162_rn(fb[j_].x, fb[j_].y); \
            __nv_bfloat162 h1_ = __floats2bfloat162_rn(fb[j_].z, fb[j_].w); \
            uint2 u_; u_.x = *(uint32_t*)&h0_; u_.y = *(uint32_t*)&h1_; \
            *(uint2*)(dst_ + j_ * 8) = u_; \
        } \
    } while (0)

    float4 fb[4];
    // prologue: B stage 0 convert+store, B stage 1 prefetch, A stages 0-2 in flight
    LOAD_B(0);
    ISSUE_A(0, 0); ISSUE_A(1, 32); ISSUE_A(2, 64);
    STS_B(0);
    LOAD_B(32);
    CP_WAIT2();
    __syncthreads();

    const int lrow = lane & 15, lhi = lane >> 4;
#pragma unroll 1
    for (int it = 0; it < 16; ++it) {
        const uint32_t As_u = smem_u + (it & 3) * ASTG;
        const uint32_t Bs_u = smem_u + BOFF + (it & 1) * BSTG;
#pragma unroll
        for (int ks = 0; ks < 2; ks++) {
            uint32_t af[4][4], bf[4][4];
#pragma unroll
            for (int mt = 0; mt < 4; mt++)
                ldsm4(af[mt], As_u + (wm * 64 + mt * 16 + lrow) * 80 + ks * 32 + lhi * 16);
#pragma unroll
            for (int np = 0; np < 4; np++)
                ldsm4(bf[np], Bs_u + (wn * 64 + np * 16 + lrow) * 80 + ks * 32 + lhi * 16);
#pragma unroll
            for (int mt = 0; mt < 4; mt++)
#pragma unroll
                for (int np = 0; np < 4; np++) {
                    mma16816(acc[mt][2 * np],
                             af[mt][0], af[mt][1], af[mt][2], af[mt][3],
                             bf[np][0], bf[np][2]);
                    mma16816(acc[mt][2 * np + 1],
                             af[mt][0], af[mt][1], af[mt][2], af[mt][3],
                             bf[np][1], bf[np][3]);
                }
        }
        if (it < 15) {
            STS_B((it + 1) & 1);              // fb holds stage it+1
            if (it < 14) LOAD_B((it + 2) * 32);
            if (it + 3 < 16) ISSUE_A((it + 3) & 3, (it + 3) * 32);
            if (it < 13) CP_WAIT2(); else if (it == 13) CP_WAIT1(); else CP_WAIT0();
            __syncthreads();
        }
    }
#undef ISSUE_A
#undef LOAD_B
#undef STS_B

    // epilogue: dist = 2 - 2*ip
#pragma unroll
    for (int mt = 0; mt < 4; mt++) {
        int r0 = wm * 64 + mt * 16 + (lane >> 2);
#pragma unroll
        for (int nt = 0; nt < 8; nt++) {
            int c = bn + wn * 64 + nt * 8 + (lane & 3) * 2;
            float2 v0, v1;
            v0.x = 2.f - 2.f * acc[mt][nt][0];
            v0.y = 2.f - 2.f * acc[mt][nt][1];
            v1.x = 2.f - 2.f * acc[mt][nt][2];
            v1.y = 2.f - 2.f * acc[mt][nt][3];
            *(float2*)(out + (size_t)r0 * K_ + c)       = v0;
            *(float2*)(out + (size_t)(r0 + 8) * K_ + c) = v1;
        }
    }
}

// ---------------- approx top-CAND per row (512 threads, depth-8 lists, prefetch) ----------------
__global__ __launch_bounds__(512)
void k_topk2(const float* __restrict__ Sa, const float* __restrict__ Sb,
             int* __restrict__ o1, int* __restrict__ o2) {
    int b = blockIdx.x;
    const float* S = (blockIdx.y == 0) ? Sa : Sb;
    int* outIdx = (blockIdx.y == 0) ? o1 : o2;
    const float4* row = (const float4*)(S + (size_t)b * K_);
    float v[TH_]; int id[TH_];
#pragma unroll
    for (int i = 0; i < TH_; i++) { v[i] = FLTMAX; id[i] = 0x7fffffff; }
    float thr = FLTMAX;
    float4 x = row[threadIdx.x];
    for (int k4 = threadIdx.x; k4 < K_ / 4; k4 += 512) {
        int k4n = k4 + 512;
        float4 nx;
        if (k4n < K_ / 4) nx = row[k4n];
        float xs[4] = {x.x, x.y, x.z, x.w};
#pragma unroll
        for (int j = 0; j < 4; j++) {
            float xv = xs[j];
            if (xv < thr) {
                int k = k4 * 4 + j;
                int pos = TH_ - 1;
                while (pos > 0 && xv < v[pos - 1]) {
                    v[pos] = v[pos - 1]; id[pos] = id[pos - 1]; pos--;
                }
                v[pos] = xv; id[pos] = k;
                thr = v[TH_ - 1];
            }
        }
        x = nx;
    }
    __shared__ float swv[16]; __shared__ int swi[16];
    __shared__ int bwi_s;
    int hp = 0;
    for (int r = 0; r < CAND_; r++) {
        float mv = (hp < TH_) ? v[hp] : FLTMAX;
        int   mi = (hp < TH_) ? id[hp] : 0x7fffffff;
        for (int o = 16; o > 0; o >>= 1) {
            float ov = __shfl_down_sync(0xffffffffu, mv, o);
            int   oi = __shfl_down_sync(0xffffffffu, mi, o);
            if (ov < mv || (ov == mv && oi < mi)) { mv = ov; mi = oi; }
        }
        if ((threadIdx.x & 31) == 0) { swv[threadIdx.x >> 5] = mv; swi[threadIdx.x >> 5] = mi; }
        __syncthreads();
        if (threadIdx.x == 0) {
            float bv = swv[0]; int bi = swi[0];
            for (int w = 1; w < 16; w++)
                if (swv[w] < bv || (swv[w] == bv && swi[w] < bi)) { bv = swv[w]; bi = swi[w]; }
            bwi_s = bi;
            outIdx[b * CAND_ + r] = bi;
        }
        __syncthreads();
        if (hp < TH_ && id[hp] == bwi_s) hp++;
        __syncthreads();
    }
}

// ---------------- exact refine: warp-per-candidate fp32 dots, then select T ----------------
template <int MODE, int T>
__global__ void k_refine(const float* __restrict__ queue, const float* __restrict__ pool,
                         const int* __restrict__ indices, const int* __restrict__ index_queue,
                         const int* __restrict__ cand, int* __restrict__ outIdx) {
    int b = blockIdx.x;
    int lane = threadIdx.x & 31, w = threadIdx.x >> 5;   // 8 warps
    __shared__ float sv[CAND_];
    const float* ar = (MODE == 0) ? (g_tnorm + b * D_) : (g_ct + b * D_);
    for (int j = w; j < CAND_; j += 8) {
        int k = cand[b * CAND_ + j];
        const float* rk;
        if (MODE == 0) rk = (k < B_) ? (g_tnorm + k * D_) : (queue + (size_t)k * D_);
        else {
            int ik = (k < B_) ? indices[k] : index_queue[k];
            rk = pool + ((size_t)g_eq[ik] * N_ + (size_t)ik) * D_;
        }
        float s = 0.f;
#pragma unroll
        for (int t = 0; t < 16; t++) { int i = t * 32 + lane; s += ar[i] * rk[i]; }
        for (int o = 16; o > 0; o >>= 1) s += __shfl_down_sync(0xffffffffu, s, o);
        if (lane == 0) sv[j] = 2.f - 2.f * s;
    }
    __syncthreads();
    if (threadIdx.x == 0) {
        float vl[CAND_]; int il[CAND_];
        for (int j = 0; j < CAND_; j++) { vl[j] = sv[j]; il[j] = cand[b * CAND_ + j]; }
        for (int r = 0; r < T; r++) {
            int best = r;
            for (int j = r + 1; j < CAND_; j++)
                if (vl[j] < vl[best] || (vl[j] == vl[best] && il[j] < il[best])) best = j;
            float tv = vl[r]; vl[r] = vl[best]; vl[best] = tv;
            int ti = il[r]; il[r] = il[best]; il[best] = ti;
            outIdx[b * T + r] = il[r];
        }
    }
}

// ---------------- final: exact con-select + loss dots + purity ----------------
__global__ void k_final(const float* __restrict__ queue,
                        const int* __restrict__ labels_bank,
                        const int* __restrict__ labels) {
    int b = blockIdx.x, t = threadIdx.x;
    __shared__ float red[256];
    __shared__ float pv[TOPKP_];
    __shared__ int conIdx[TOPK_];
    const float* qr = g_qnorm + b * D_;
    const float* tr = g_tnorm + b * D_;
    for (int j = 0; j < TOPKP_; j++) {
        int k = g_idxp[b * TOPKP_ + j];
        const float* rk = (k < B_) ? (g_tnorm + k * D_) : (queue + (size_t)k * D_);
        red[t] = tr[t] * rk[t] + tr[t + 256] * rk[t + 256];
        __syncthreads();
        for (int s = 128; s > 0; s >>= 1) { if (t < s) red[t] += red[t + s]; __syncthreads(); }
        if (t == 0) pv[j] = 2.f - 2.f * red[0];
        __syncthreads();
    }
    if (t == 0) {
        float vl[TOPKP_]; int il[TOPKP_];
        for (int j = 0; j < TOPKP_; j++) { vl[j] = pv[j]; il[j] = g_idxp[b * TOPKP_ + j]; }
        for (int r = 0; r < TOPK_; r++) {
            int best = r;
            for (int j = r + 1; j < TOPKP_; j++)
                if (vl[j] < vl[best] || (vl[j] == vl[best] && il[j] < il[best])) best = j;
            float tv = vl[r]; vl[r] = vl[best]; vl[best] = tv;
            int ti = il[r]; il[r] = il[best]; il[best] = ti;
            conIdx[r] = il[r];
        }
    }
    __syncthreads();
    __shared__ float s_un, s_con;
    __shared__ int s_match;
    if (t == 0) { s_un = 0.f; s_con = 0.f; s_match = 0; }
    __syncthreads();
    for (int j = 0; j < 2 * TOPK_; j++) {
        int k = (j < TOPK_) ? g_unidx[b * TOPK_ + j] : conIdx[j - TOPK_];
        const float* rk = (k < B_) ? (g_tnorm + k * D_) : (queue + (size_t)k * D_);
        red[t] = qr[t] * rk[t] + qr[t + 256] * rk[t + 256];
        __syncthreads();
        for (int s = 128; s > 0; s >>= 1) { if (t < s) red[t] += red[t + s]; __syncthreads(); }
        if (t == 0) {
            float d = 2.f - 2.f * red[0];
            if (j < TOPK_) {
                s_un += d;
                int lab = (k < B_) ? labels[k] : labels_bank[k];
                if (lab == labels[b]) s_match++;
            } else {
                s_con += d;
            }
        }
        __syncthreads();
    }
    if (t == 0) {
        g_pb_un[b]  = s_un / (float)TOPK_;
        g_pb_con[b] = s_con / (float)TOPK_;
        g_pb_pur[b] = (float)s_match / (float)TOPK_;
    }
}

__global__ void k_finalize(float* __restrict__ out, int out_size) {
    float su = 0.f, sc = 0.f, sp = 0.f;
    for (int b = 0; b < B_; b++) { su += g_pb_un[b]; sc += g_pb_con[b]; sp += g_pb_pur[b]; }
    float loss = (sc / (float)B_ + su / (float)B_) * 0.5f;
    out[0] = loss;
    if (out_size > 1) out[1] = sp / (float)B_;
}

// ---------------- launch ----------------
extern "C" void kernel_launch(void* const* d_in, const int* in_sizes, int n_in,
                              void* d_out, int out_size) {
    const float* query       = (const float*)d_in[0];
    const float* ctgt        = (const float*)d_in[1];
    const float* queue       = (const float*)d_in[2];
    const float* pool        = (const float*)d_in[3];
    const int*   labels_bank = (const int*)d_in[4];
    const int*   index_queue = (const int*)d_in[5];
    const int*   pool_qindex = (const int*)d_in[6];
    const int*   labels      = (const int*)d_in[7];
    const int*   indices     = (const int*)d_in[8];

    float* St_ptr;  cudaGetSymbolAddress((void**)&St_ptr,  g_St);
    float* Stp_ptr; cudaGetSymbolAddress((void**)&Stp_ptr, g_Stp);
    int* c1_ptr;    cudaGetSymbolAddress((void**)&c1_ptr,  g_cand1);
    int* c2_ptr;    cudaGetSymbolAddress((void**)&c2_ptr,  g_cand2);
    int* un_ptr;    cudaGetSymbolAddress((void**)&un_ptr,  g_unidx);
    int* ip_ptr;    cudaGetSymbolAddress((void**)&ip_ptr,  g_idxp);

    cudaFuncSetAttribute(k_gemm3, cudaFuncAttributeMaxDynamicSharedMemorySize, GSMEM);

    k_eq_copy<<<(N_ + 255) / 256, 256>>>(pool_qindex);
    k_eq_set<<<1, 256>>>(indices, pool_qindex);
    k_norm<<<B_, 256>>>(query, ctgt);
    k_gather_ct<<<B_, 128>>>(pool, indices);

    dim3 gg(K_ / BN, 2);
    k_gemm3<<<gg, 256, GSMEM>>>(queue, pool, indices, index_queue, St_ptr, Stp_ptr);

    dim3 gt(B_, 2);
    k_topk2<<<gt, 512>>>(St_ptr, Stp_ptr, c1_ptr, c2_ptr);

    k_refine<0, TOPK_ ><<<B_, 256>>>(queue, pool, indices, index_queue, c1_ptr, un_ptr);
    k_refine<1, TOPKP_><<<B_, 256>>>(queue, pool, indices, index_queue, c2_ptr, ip_ptr);

    k_final<<<B_, 256>>>(queue, labels_bank, labels);
    k_finalize<<<1, 1>>>((float*)d_out, out_size);
}